// round 1
// baseline (speedup 1.0000x reference)
#include <cuda_runtime.h>

#define T_STEPS 50
#define BATCH   128
#define NIN     16384
#define NH      256
#define NO      11
#define M_TOT   (T_STEPS * BATCH)   // 6400

// Scratch for CUR1 = X @ W1^T + b1, laid out [T, B, NH] (row m = t*BATCH + b)
__device__ float g_cur1[M_TOT * NH];

// ---------------------------------------------------------------------------
// GEMM: out[m][n] = sum_k X[m][k] * W1[n][k] + b1[n]
// M=6400, N=256, K=16384.  Tile 64x64, BK=16, 128 threads, microtile 8x4.
// FMA-bound by design: per k-slice per thread = 32 FFMA vs 3 LDS.128.
// ---------------------------------------------------------------------------
#define BM  64
#define BN  64
#define BKK 16
#define PAD 4

__global__ __launch_bounds__(128) void gemm_x_w1(
    const float* __restrict__ X,
    const float* __restrict__ W1,
    const float* __restrict__ b1,
    float* __restrict__ out)
{
    __shared__ float As[BKK][BM + PAD];  // [k][m]
    __shared__ float Bs[BKK][BN + PAD];  // [k][n]

    const int tid = threadIdx.x;           // 0..127
    const int tx  = tid & 15;              // 0..15 -> 4 cols each
    const int ty  = tid >> 4;              // 0..7  -> 8 rows each
    const int m0  = blockIdx.y * BM;
    const int n0  = blockIdx.x * BN;

    // loader mapping: each thread loads 8 consecutive floats (2 float4) of one row
    const int lr = tid >> 1;               // 0..63
    const int lc = (tid & 1) * 8;          // 0 or 8

    const float* __restrict__ aptr = X  + (size_t)(m0 + lr) * NIN + lc;
    const float* __restrict__ bptr = W1 + (size_t)(n0 + lr) * NIN + lc;

    float acc[8][4];
#pragma unroll
    for (int i = 0; i < 8; i++)
#pragma unroll
        for (int j = 0; j < 4; j++) acc[i][j] = 0.0f;

    // prefetch chunk 0 into registers
    float4 a0 = *reinterpret_cast<const float4*>(aptr + 0);
    float4 a1 = *reinterpret_cast<const float4*>(aptr + 4);
    float4 b0 = *reinterpret_cast<const float4*>(bptr + 0);
    float4 b1v = *reinterpret_cast<const float4*>(bptr + 4);

    for (int k0 = 0; k0 < NIN; k0 += BKK) {
        // stage current regs -> shared (transposed to [k][row])
        As[lc + 0][lr] = a0.x; As[lc + 1][lr] = a0.y;
        As[lc + 2][lr] = a0.z; As[lc + 3][lr] = a0.w;
        As[lc + 4][lr] = a1.x; As[lc + 5][lr] = a1.y;
        As[lc + 6][lr] = a1.z; As[lc + 7][lr] = a1.w;
        Bs[lc + 0][lr] = b0.x; Bs[lc + 1][lr] = b0.y;
        Bs[lc + 2][lr] = b0.z; Bs[lc + 3][lr] = b0.w;
        Bs[lc + 4][lr] = b1v.x; Bs[lc + 5][lr] = b1v.y;
        Bs[lc + 6][lr] = b1v.z; Bs[lc + 7][lr] = b1v.w;
        __syncthreads();

        // prefetch next chunk (hides DRAM/L2 latency behind the compute below)
        if (k0 + BKK < NIN) {
            const float* ap = aptr + k0 + BKK;
            const float* bp = bptr + k0 + BKK;
            a0  = *reinterpret_cast<const float4*>(ap + 0);
            a1  = *reinterpret_cast<const float4*>(ap + 4);
            b0  = *reinterpret_cast<const float4*>(bp + 0);
            b1v = *reinterpret_cast<const float4*>(bp + 4);
        }

#pragma unroll
        for (int kk = 0; kk < BKK; kk++) {
            float a[8], b[4];
            float4 av0 = *reinterpret_cast<const float4*>(&As[kk][ty * 8 + 0]);
            float4 av1 = *reinterpret_cast<const float4*>(&As[kk][ty * 8 + 4]);
            float4 bv  = *reinterpret_cast<const float4*>(&Bs[kk][tx * 4]);
            a[0] = av0.x; a[1] = av0.y; a[2] = av0.z; a[3] = av0.w;
            a[4] = av1.x; a[5] = av1.y; a[6] = av1.z; a[7] = av1.w;
            b[0] = bv.x;  b[1] = bv.y;  b[2] = bv.z;  b[3] = bv.w;
#pragma unroll
            for (int i = 0; i < 8; i++)
#pragma unroll
                for (int j = 0; j < 4; j++)
                    acc[i][j] = fmaf(a[i], b[j], acc[i][j]);
        }
        __syncthreads();
    }

    // epilogue: add bias, vectorized store
    float4 bias = *reinterpret_cast<const float4*>(b1 + n0 + tx * 4);
#pragma unroll
    for (int i = 0; i < 8; i++) {
        const int m = m0 + ty * 8 + i;
        float4 v;
        v.x = acc[i][0] + bias.x;
        v.y = acc[i][1] + bias.y;
        v.z = acc[i][2] + bias.z;
        v.w = acc[i][3] + bias.w;
        *reinterpret_cast<float4*>(out + (size_t)m * NH + n0 + tx * 4) = v;
    }
}

// ---------------------------------------------------------------------------
// Sequential scan over T. One CTA per batch element (batch elems independent).
// 256 threads: thread j owns mem1[j]. Layer-2 (256 -> 11) via deterministic
// butterfly shuffle reductions; threads 0..10 own mem2[o].
// ---------------------------------------------------------------------------
__global__ __launch_bounds__(256) void snn_scan(
    const float* __restrict__ cur1,
    const float* __restrict__ W2,
    const float* __restrict__ b2,
    float* __restrict__ out)
{
    const int b   = blockIdx.x;
    const int j   = threadIdx.x;          // hidden neuron index
    const int wid = j >> 5;               // 0..7
    const int lid = j & 31;

    __shared__ float warp_sums[8][NO + 1];

    // preload W2 column j (11 values) into registers
    float w2c[NO];
#pragma unroll
    for (int o = 0; o < NO; o++) w2c[o] = W2[o * NH + j];

    float mem1 = 0.0f;
    float mem2 = 0.0f;                    // only meaningful for j < NO
    const float bias2 = (j < NO) ? b2[j] : 0.0f;

    for (int t = 0; t < T_STEPS; t++) {
        // layer 1 membrane update
        const float c1 = cur1[((size_t)t * BATCH + b) * NH + j];
        mem1 = 0.9f * mem1 + c1;
        const float spk1 = (mem1 - 1.0f > 0.0f) ? 1.0f : 0.0f;
        mem1 -= spk1;

        // partial products for the 11 outputs
        float p[NO];
#pragma unroll
        for (int o = 0; o < NO; o++) p[o] = spk1 * w2c[o];

        // deterministic warp butterfly reduction for each output
#pragma unroll
        for (int o = 0; o < NO; o++) {
#pragma unroll
            for (int off = 16; off > 0; off >>= 1)
                p[o] += __shfl_xor_sync(0xFFFFFFFFu, p[o], off);
        }
        if (lid == 0) {
#pragma unroll
            for (int o = 0; o < NO; o++) warp_sums[wid][o] = p[o];
        }
        __syncthreads();

        if (j < NO) {
            float c2 = bias2;
#pragma unroll
            for (int w = 0; w < 8; w++) c2 += warp_sums[w][j];
            mem2 = 0.9f * mem2 + c2;
            const float spk2 = (mem2 - 1.0f > 0.0f) ? 1.0f : 0.0f;
            mem2 -= spk2;
            out[((size_t)t * BATCH + b) * NO + j] = spk2;
        }
        __syncthreads();
    }
}

// ---------------------------------------------------------------------------
extern "C" void kernel_launch(void* const* d_in, const int* in_sizes, int n_in,
                              void* d_out, int out_size)
{
    const float* x  = (const float*)d_in[0];   // [50,128,128,128]
    const float* W1 = (const float*)d_in[1];   // [256,16384]
    const float* b1 = (const float*)d_in[2];   // [256]
    const float* W2 = (const float*)d_in[3];   // [11,256]
    const float* b2 = (const float*)d_in[4];   // [11]
    float* out = (float*)d_out;                // [50,128,11]

    float* cur1;
    cudaGetSymbolAddress((void**)&cur1, g_cur1);

    dim3 ggrid(NH / BN, M_TOT / BM);   // (4, 100)
    gemm_x_w1<<<ggrid, 128>>>(x, W1, b1, cur1);

    snn_scan<<<BATCH, NH>>>(cur1, W2, b2, out);
}